// round 14
// baseline (speedup 1.0000x reference)
#include <cuda_runtime.h>
#include <math.h>

#define NMAX 50000
#define EMAX 800000
#define DF   96
#define SLOTW 64            // fixed slot width per row (max degree headroom)

// Scratch (allocation-free: __device__ globals). 16B-aligned.
__device__ __align__(16) float g_h[NMAX * DF];         // projected features (fp32)
__device__ __align__(16) int   g_cnt[NMAX];            // per-row degree (zero at entry)
__device__ __align__(16) int2  g_slot[NMAX * SLOTW];   // direct slots (25.6 MB)

// ---------------- dense projection: h = x @ W + b (FFMA2 path) -----------
// blockDim = (32, 8). Block tile: 32 rows x 96 cols.
// Thread: 4 rows (2 packed pairs) x 3 cols = 6 FFMA2 per k.
__global__ void gemm_kernel(const float* __restrict__ x,
                            const float* __restrict__ W,
                            const float* __restrict__ b,
                            int N) {
    __shared__ float Ws[DF * DF];          // 36 KB
    __shared__ float xs_t[DF][34];         // transposed rows, pad 34: ~12.8 KB

    const int tx  = threadIdx.x;           // 0..31 (col lane)
    const int ty  = threadIdx.y;           // 0..7  (row group)
    const int tid = ty * 32 + tx;

    for (int i = tid; i < DF * DF; i += 256) Ws[i] = W[i];

    const float b0 = b[tx];
    const float b1 = b[tx + 32];
    const float b2 = b[tx + 64];

    const int tile = blockIdx.x * 32;
    if (tile >= N) return;

    // coalesced gmem read, transposed smem write (2-way conflict, pad 34)
    for (int i = tid; i < 32 * DF; i += 256) {
        int r = i / DF, c = i % DF;
        int gr = tile + r;
        xs_t[c][r] = (gr < N) ? x[(size_t)gr * DF + c] : 0.0f;
    }
    __syncthreads();

    const int r0 = ty * 4;                 // even → 8B-aligned pair loads
    unsigned long long acc[2][3];
#pragma unroll
    for (int p = 0; p < 2; p++)
#pragma unroll
        for (int c = 0; c < 3; c++) acc[p][c] = 0ULL;

#pragma unroll 4
    for (int k = 0; k < DF; k++) {
        float w0 = Ws[k * DF + tx];
        float w1 = Ws[k * DF + tx + 32];
        float w2 = Ws[k * DF + tx + 64];
        unsigned long long w0p, w1p, w2p;
        asm("mov.b64 %0, {%1, %1};" : "=l"(w0p) : "f"(w0));
        asm("mov.b64 %0, {%1, %1};" : "=l"(w1p) : "f"(w1));
        asm("mov.b64 %0, {%1, %1};" : "=l"(w2p) : "f"(w2));
        // packed row pairs {r0, r0+1} and {r0+2, r0+3} (broadcast LDS.64)
        unsigned long long x0p = *(const unsigned long long*)&xs_t[k][r0];
        unsigned long long x1p = *(const unsigned long long*)&xs_t[k][r0 + 2];
        asm("fma.rn.f32x2 %0, %1, %2, %0;" : "+l"(acc[0][0]) : "l"(x0p), "l"(w0p));
        asm("fma.rn.f32x2 %0, %1, %2, %0;" : "+l"(acc[0][1]) : "l"(x0p), "l"(w1p));
        asm("fma.rn.f32x2 %0, %1, %2, %0;" : "+l"(acc[0][2]) : "l"(x0p), "l"(w2p));
        asm("fma.rn.f32x2 %0, %1, %2, %0;" : "+l"(acc[1][0]) : "l"(x1p), "l"(w0p));
        asm("fma.rn.f32x2 %0, %1, %2, %0;" : "+l"(acc[1][1]) : "l"(x1p), "l"(w1p));
        asm("fma.rn.f32x2 %0, %1, %2, %0;" : "+l"(acc[1][2]) : "l"(x1p), "l"(w2p));
    }

#pragma unroll
    for (int p = 0; p < 2; p++) {
        float lo0, hi0, lo1, hi1, lo2, hi2;
        asm("mov.b64 {%0, %1}, %2;" : "=f"(lo0), "=f"(hi0) : "l"(acc[p][0]));
        asm("mov.b64 {%0, %1}, %2;" : "=f"(lo1), "=f"(hi1) : "l"(acc[p][1]));
        asm("mov.b64 {%0, %1}, %2;" : "=f"(lo2), "=f"(hi2) : "l"(acc[p][2]));
        int grA = tile + r0 + 2 * p;       // lo = first row of pair
        int grB = grA + 1;
        if (grA < N) {
            float* hp = &g_h[(size_t)grA * DF];
            hp[tx] = lo0 + b0; hp[tx + 32] = lo1 + b1; hp[tx + 64] = lo2 + b2;
        }
        if (grB < N) {
            float* hp = &g_h[(size_t)grB * DF];
            hp[tx] = hi0 + b0; hp[tx + 32] = hi1 + b1; hp[tx + 64] = hi2 + b2;
        }
    }
}

// ---------------- direct slot scatter (replaces hist+alloc+scatter) ------
// g_cnt is zero on entry (module-load init / reset by gather each call).
__global__ void scatter_kernel(const int* __restrict__ row,
                               const int* __restrict__ col,
                               const float* __restrict__ w, int E) {
    const int E4 = E >> 2;
    const int4*   r4 = (const int4*)row;
    const int4*   c4 = (const int4*)col;
    const float4* w4 = (const float4*)w;
    for (int i = blockIdx.x * blockDim.x + threadIdx.x; i < E4;
         i += gridDim.x * blockDim.x) {
        int4   r = r4[i];
        int4   c = c4[i];
        float4 wv = w4[i];
        int s0 = atomicAdd(&g_cnt[r.x], 1);
        int s1 = atomicAdd(&g_cnt[r.y], 1);
        int s2 = atomicAdd(&g_cnt[r.z], 1);
        int s3 = atomicAdd(&g_cnt[r.w], 1);
        if (s0 < SLOTW) g_slot[r.x * SLOTW + s0] = make_int2(c.x, __float_as_int(wv.x));
        if (s1 < SLOTW) g_slot[r.y * SLOTW + s1] = make_int2(c.y, __float_as_int(wv.y));
        if (s2 < SLOTW) g_slot[r.z * SLOTW + s2] = make_int2(c.z, __float_as_int(wv.z));
        if (s3 < SLOTW) g_slot[r.w * SLOTW + s3] = make_int2(c.w, __float_as_int(wv.w));
    }
    for (int i = (E4 << 2) + blockIdx.x * blockDim.x + threadIdx.x; i < E;
         i += gridDim.x * blockDim.x) {
        int s = atomicAdd(&g_cnt[row[i]], 1);
        if (s < SLOTW) g_slot[row[i] * SLOTW + s] = make_int2(col[i], __float_as_int(w[i]));
    }
}

// ---------------- warp-per-row gather + ELU (int4 pair loads) ------------
__global__ void gather_kernel(float* __restrict__ out, int N) {
    const int gwarp = (blockIdx.x * blockDim.x + threadIdx.x) >> 5;
    const int lane  = threadIdx.x & 31;
    if (gwarp >= N) return;

    int len = g_cnt[gwarp];
    if (len > SLOTW) len = SLOTW;
    if (lane == 0) g_cnt[gwarp] = 0;       // restore zero invariant (after read)

    const int2* sp = &g_slot[gwarp * SLOTW];   // 512B-aligned base

    float a0 = 0.f, a1 = 0.f, a2 = 0.f;
    int i = 0;
    for (; i + 3 < len; i += 4) {
        const int4 pa = *(const int4*)&sp[i];       // edges i, i+1
        const int4 pb = *(const int4*)&sp[i + 2];   // edges i+2, i+3
        const float* h0 = &g_h[(size_t)pa.x * DF];
        const float* h1 = &g_h[(size_t)pa.z * DF];
        const float* h2 = &g_h[(size_t)pb.x * DF];
        const float* h3 = &g_h[(size_t)pb.z * DF];
        float p00 = h0[lane], p01 = h0[lane + 32], p02 = h0[lane + 64];
        float p10 = h1[lane], p11 = h1[lane + 32], p12 = h1[lane + 64];
        float p20 = h2[lane], p21 = h2[lane + 32], p22 = h2[lane + 64];
        float p30 = h3[lane], p31 = h3[lane + 32], p32 = h3[lane + 64];
        const float w0 = __int_as_float(pa.y);
        const float w1 = __int_as_float(pa.w);
        const float w2 = __int_as_float(pb.y);
        const float w3 = __int_as_float(pb.w);
        a0 = fmaf(w0, p00, a0); a1 = fmaf(w0, p01, a1); a2 = fmaf(w0, p02, a2);
        a0 = fmaf(w1, p10, a0); a1 = fmaf(w1, p11, a1); a2 = fmaf(w1, p12, a2);
        a0 = fmaf(w2, p20, a0); a1 = fmaf(w2, p21, a1); a2 = fmaf(w2, p22, a2);
        a0 = fmaf(w3, p30, a0); a1 = fmaf(w3, p31, a1); a2 = fmaf(w3, p32, a2);
    }
    for (; i < len; i++) {
        const int2 e0 = sp[i];
        const float wv = __int_as_float(e0.y);
        const float* hp = &g_h[(size_t)e0.x * DF];
        a0 = fmaf(wv, hp[lane],      a0);
        a1 = fmaf(wv, hp[lane + 32], a1);
        a2 = fmaf(wv, hp[lane + 64], a2);
    }

    float* pre = out;
    float* act = out + (size_t)N * DF;
    const int o = gwarp * DF + lane;
    pre[o]      = a0;
    pre[o + 32] = a1;
    pre[o + 64] = a2;
    act[o]      = (a0 > 0.f) ? a0 : expm1f(a0);
    act[o + 32] = (a1 > 0.f) ? a1 : expm1f(a1);
    act[o + 64] = (a2 > 0.f) ? a2 : expm1f(a2);
}

// ---------------- launch ----------------
extern "C" void kernel_launch(void* const* d_in, const int* in_sizes, int n_in,
                              void* d_out, int out_size) {
    const float* x  = (const float*)d_in[0];
    const float* W  = (const float*)d_in[1];
    const float* b  = (const float*)d_in[2];
    const int*   ei = (const int*)d_in[3];
    const float* ew = (const float*)d_in[4];
    float* out = (float*)d_out;

    const int N = in_sizes[0] / DF;
    const int E = in_sizes[4];
    const int* row = ei;         // edge_index[0]
    const int* col = ei + E;     // edge_index[1]

    // One-time side-stream + events (created during the uncaptured
    // correctness call; no device memory allocated anywhere).
    static cudaStream_t s_side = nullptr;
    static cudaEvent_t  ev_fork = nullptr, ev_join = nullptr;
    if (s_side == nullptr) {
        cudaStreamCreateWithFlags(&s_side, cudaStreamNonBlocking);
        cudaEventCreateWithFlags(&ev_fork, cudaEventDisableTiming);
        cudaEventCreateWithFlags(&ev_join, cudaEventDisableTiming);
    }

    // Fork: GEMM on side stream, concurrent with the slot scatter.
    cudaEventRecord(ev_fork, 0);
    cudaStreamWaitEvent(s_side, ev_fork, 0);
    dim3 gblk(32, 8);
    gemm_kernel<<<(N + 31) / 32, gblk, 0, s_side>>>(x, W, b, N);
    cudaEventRecord(ev_join, s_side);

    // Single-pass slot scatter on main (captured) stream.
    const int E4 = E >> 2;
    scatter_kernel<<<(E4 + 255) / 256, 256>>>(row, col, ew, E);

    // Join: gather needs both g_h (GEMM) and the slots (scatter).
    cudaStreamWaitEvent(0, ev_join, 0);
    const int threads = 256;
    gather_kernel<<<((size_t)N * 32 + threads - 1) / threads, threads>>>(out, N);
}

// round 15
// speedup vs baseline: 1.9011x; 1.9011x over previous
#include <cuda_runtime.h>
#include <math.h>

#define NMAX 50000
#define EMAX 800000
#define DF   96
// scan: 256 threads x 4 elems = 1024 elems per block
#define SCAN_T 256
#define SCAN_E 1024

// Scratch (allocation-free: __device__ globals). 16B-aligned for int4 access.
__device__ __align__(16) float g_h[NMAX * DF];     // projected features
__device__ __align__(16) int   g_cnt[NMAX];        // per-row degree (zero at entry)
__device__ __align__(16) int   g_offs[NMAX + 4];   // CSR offsets (padded)
__device__ __align__(16) int   g_cur[NMAX];        // scatter cursors
__device__ int   g_part[64];                       // per-block scan partials
__device__ __align__(16) int2  g_e[EMAX];          // packed (col, w-bits) per slot

// ---------------- dense projection: h = x @ W + b ----------------
// blockDim = (32, 8). Block tile: 32 rows x 96 cols. Thread: 4 rows x 3 cols.
__global__ void gemm_kernel(const float* __restrict__ x,
                            const float* __restrict__ W,
                            const float* __restrict__ b,
                            int N) {
    __shared__ float Ws[DF * DF];      // 36 KB
    __shared__ float xs[32][DF];       // 12 KB

    const int tx  = threadIdx.x;
    const int ty  = threadIdx.y;
    const int tid = ty * 32 + tx;

    for (int i = tid; i < DF * DF; i += 256) Ws[i] = W[i];

    const float b0 = b[tx];
    const float b1 = b[tx + 32];
    const float b2 = b[tx + 64];

    const int tile = blockIdx.x * 32;
    if (tile >= N) return;

    for (int i = tid; i < 32 * DF; i += 256) {
        int r = i / DF, c = i % DF;
        int gr = tile + r;
        xs[r][c] = (gr < N) ? x[(size_t)gr * DF + c] : 0.0f;
    }
    __syncthreads();

    const int r0 = ty * 4;
    float a[4][3];
#pragma unroll
    for (int j = 0; j < 4; j++) { a[j][0] = 0.f; a[j][1] = 0.f; a[j][2] = 0.f; }

#pragma unroll 4
    for (int k = 0; k < DF; k++) {
        float w0 = Ws[k * DF + tx];
        float w1 = Ws[k * DF + tx + 32];
        float w2 = Ws[k * DF + tx + 64];
#pragma unroll
        for (int j = 0; j < 4; j++) {
            float xv = xs[r0 + j][k];
            a[j][0] = fmaf(xv, w0, a[j][0]);
            a[j][1] = fmaf(xv, w1, a[j][1]);
            a[j][2] = fmaf(xv, w2, a[j][2]);
        }
    }

#pragma unroll
    for (int j = 0; j < 4; j++) {
        int gr = tile + r0 + j;
        if (gr < N) {
            float* hp = &g_h[(size_t)gr * DF];
            hp[tx]      = a[j][0] + b0;
            hp[tx + 32] = a[j][1] + b1;
            hp[tx + 64] = a[j][2] + b2;
        }
    }
}

// ---------------- degree histogram (int4 vectorized) ----------------
// g_cnt is zero on entry (module-load init / restored by scan3 each call).
__global__ void hist_kernel(const int* __restrict__ row, int E) {
    const int E4 = E >> 2;
    const int4* r4 = (const int4*)row;
    for (int i = blockIdx.x * blockDim.x + threadIdx.x; i < E4;
         i += gridDim.x * blockDim.x) {
        int4 v = r4[i];
        atomicAdd(&g_cnt[v.x], 1);
        atomicAdd(&g_cnt[v.y], 1);
        atomicAdd(&g_cnt[v.z], 1);
        atomicAdd(&g_cnt[v.w], 1);
    }
    for (int i = (E4 << 2) + blockIdx.x * blockDim.x + threadIdx.x; i < E;
         i += gridDim.x * blockDim.x) {
        atomicAdd(&g_cnt[row[i]], 1);
    }
}

// ---------------- scan phase 1: block-local exclusive scan (int4) --------
__global__ void scan1_kernel(int n) {
    __shared__ int warpsum[8];
    const int tid  = threadIdx.x;            // 0..255
    const int lane = tid & 31;
    const int wid  = tid >> 5;
    const int e0   = blockIdx.x * SCAN_E + tid * 4;

    int4 v;
    v.x = (e0     < n) ? g_cnt[e0]     : 0;
    v.y = (e0 + 1 < n) ? g_cnt[e0 + 1] : 0;
    v.z = (e0 + 2 < n) ? g_cnt[e0 + 2] : 0;
    v.w = (e0 + 3 < n) ? g_cnt[e0 + 3] : 0;
    const int tsum = v.x + v.y + v.z + v.w;

    // warp inclusive scan of per-thread sums
    int inc = tsum;
#pragma unroll
    for (int d = 1; d < 32; d <<= 1) {
        int t = __shfl_up_sync(0xFFFFFFFFu, inc, d);
        if (lane >= d) inc += t;
    }
    if (lane == 31) warpsum[wid] = inc;
    __syncthreads();
    if (tid < 8) {
        int ws = warpsum[tid];
#pragma unroll
        for (int d = 1; d < 8; d <<= 1) {
            int t = __shfl_up_sync(0xFFu, ws, d);
            if ((tid & 7) >= d) ws += t;
        }
        warpsum[tid] = ws;
    }
    __syncthreads();

    const int base = ((wid > 0) ? warpsum[wid - 1] : 0) + inc - tsum;

    if (e0 + 3 < n) {
        int4 o;
        o.x = base;
        o.y = base + v.x;
        o.z = o.y + v.y;
        o.w = o.z + v.z;
        *(int4*)&g_offs[e0] = o;
    } else {
        int run = base;
        if (e0     < n) { g_offs[e0]     = run; run += v.x; }
        if (e0 + 1 < n) { g_offs[e0 + 1] = run; run += v.y; }
        if (e0 + 2 < n) { g_offs[e0 + 2] = run; run += v.z; }
        if (e0 + 3 < n) { g_offs[e0 + 3] = run; }
    }
    if (tid == SCAN_T - 1) g_part[blockIdx.x] = warpsum[7];
}

// ---------------- scan phase 2: exclusive scan of <=64 block partials ----
__global__ void scan2_kernel(int nb) {
    const int t = threadIdx.x;          // blockDim = 64
    int v = (t < nb) ? g_part[t] : 0;
    int inc = v;
    const unsigned full = 0xFFFFFFFFu;
#pragma unroll
    for (int d = 1; d < 32; d <<= 1) {
        int u = __shfl_up_sync(full, inc, d);
        if ((t & 31) >= d) inc += u;
    }
    __shared__ int w0sum;
    if (t == 31) w0sum = inc;
    __syncthreads();
    int base = (t >= 32) ? w0sum : 0;
    g_part[t] = base + inc - v;          // exclusive
}

// ---------------- scan phase 3: add base, init cursors, re-zero cnt ------
__global__ void scan3_kernel(int n, int E) {
    const int tid = threadIdx.x;
    const int e0  = blockIdx.x * SCAN_E + tid * 4;
    const int base = g_part[blockIdx.x];
    const int4 z = make_int4(0, 0, 0, 0);

    if (e0 + 3 < n) {
        int4 o = *(const int4*)&g_offs[e0];
        o.x += base; o.y += base; o.z += base; o.w += base;
        *(int4*)&g_offs[e0] = o;
        *(int4*)&g_cur[e0]  = o;
        *(int4*)&g_cnt[e0]  = z;         // restore invariant for next call
    } else {
#pragma unroll
        for (int j = 0; j < 4; j++) {
            int i = e0 + j;
            if (i < n) {
                int o = g_offs[i] + base;
                g_offs[i] = o;
                g_cur[i]  = o;
                g_cnt[i]  = 0;
            }
        }
    }
    if (e0 == 0) g_offs[n] = E;
}

// ---------------- bucket scatter into CSR slots (vectorized reads) -------
__global__ void scatter_kernel(const int* __restrict__ row,
                               const int* __restrict__ col,
                               const float* __restrict__ w, int E) {
    const int E4 = E >> 2;
    const int4*   r4 = (const int4*)row;
    const int4*   c4 = (const int4*)col;
    const float4* w4 = (const float4*)w;
    for (int i = blockIdx.x * blockDim.x + threadIdx.x; i < E4;
         i += gridDim.x * blockDim.x) {
        int4   r = r4[i];
        int4   c = c4[i];
        float4 wv = w4[i];
        int p;
        p = atomicAdd(&g_cur[r.x], 1); g_e[p] = make_int2(c.x, __float_as_int(wv.x));
        p = atomicAdd(&g_cur[r.y], 1); g_e[p] = make_int2(c.y, __float_as_int(wv.y));
        p = atomicAdd(&g_cur[r.z], 1); g_e[p] = make_int2(c.z, __float_as_int(wv.z));
        p = atomicAdd(&g_cur[r.w], 1); g_e[p] = make_int2(c.w, __float_as_int(wv.w));
    }
    for (int i = (E4 << 2) + blockIdx.x * blockDim.x + threadIdx.x; i < E;
         i += gridDim.x * blockDim.x) {
        int p = atomicAdd(&g_cur[row[i]], 1);
        g_e[p] = make_int2(col[i], __float_as_int(w[i]));
    }
}

// ---------------- warp-per-row gather + ELU (x4 unroll) ----------------
__global__ void gather_kernel(float* __restrict__ out, int N) {
    const int gwarp = (blockIdx.x * blockDim.x + threadIdx.x) >> 5;
    const int lane  = threadIdx.x & 31;
    if (gwarp >= N) return;

    const int s = g_offs[gwarp];
    const int e = g_offs[gwarp + 1];

    float a0 = 0.f, a1 = 0.f, a2 = 0.f;
    int i = s;
    for (; i + 3 < e; i += 4) {
        const int2 e0 = g_e[i];
        const int2 e1 = g_e[i + 1];
        const int2 e2 = g_e[i + 2];
        const int2 e3 = g_e[i + 3];
        const float* h0 = &g_h[(size_t)e0.x * DF];
        const float* h1 = &g_h[(size_t)e1.x * DF];
        const float* h2 = &g_h[(size_t)e2.x * DF];
        const float* h3 = &g_h[(size_t)e3.x * DF];
        float p00 = h0[lane], p01 = h0[lane + 32], p02 = h0[lane + 64];
        float p10 = h1[lane], p11 = h1[lane + 32], p12 = h1[lane + 64];
        float p20 = h2[lane], p21 = h2[lane + 32], p22 = h2[lane + 64];
        float p30 = h3[lane], p31 = h3[lane + 32], p32 = h3[lane + 64];
        const float w0 = __int_as_float(e0.y);
        const float w1 = __int_as_float(e1.y);
        const float w2 = __int_as_float(e2.y);
        const float w3 = __int_as_float(e3.y);
        a0 = fmaf(w0, p00, a0); a1 = fmaf(w0, p01, a1); a2 = fmaf(w0, p02, a2);
        a0 = fmaf(w1, p10, a0); a1 = fmaf(w1, p11, a1); a2 = fmaf(w1, p12, a2);
        a0 = fmaf(w2, p20, a0); a1 = fmaf(w2, p21, a1); a2 = fmaf(w2, p22, a2);
        a0 = fmaf(w3, p30, a0); a1 = fmaf(w3, p31, a1); a2 = fmaf(w3, p32, a2);
    }
    for (; i < e; i++) {
        const int2 e0 = g_e[i];
        const float wv = __int_as_float(e0.y);
        const float* hp = &g_h[(size_t)e0.x * DF];
        a0 = fmaf(wv, hp[lane],      a0);
        a1 = fmaf(wv, hp[lane + 32], a1);
        a2 = fmaf(wv, hp[lane + 64], a2);
    }

    float* pre = out;
    float* act = out + (size_t)N * DF;
    const int o = gwarp * DF + lane;
    pre[o]      = a0;
    pre[o + 32] = a1;
    pre[o + 64] = a2;
    act[o]      = (a0 > 0.f) ? a0 : expm1f(a0);
    act[o + 32] = (a1 > 0.f) ? a1 : expm1f(a1);
    act[o + 64] = (a2 > 0.f) ? a2 : expm1f(a2);
}

// ---------------- launch ----------------
extern "C" void kernel_launch(void* const* d_in, const int* in_sizes, int n_in,
                              void* d_out, int out_size) {
    const float* x  = (const float*)d_in[0];
    const float* W  = (const float*)d_in[1];
    const float* b  = (const float*)d_in[2];
    const int*   ei = (const int*)d_in[3];
    const float* ew = (const float*)d_in[4];
    float* out = (float*)d_out;

    const int N = in_sizes[0] / DF;
    const int E = in_sizes[4];
    const int* row = ei;         // edge_index[0]
    const int* col = ei + E;     // edge_index[1]

    const int nScanBlocks = (N + SCAN_E - 1) / SCAN_E;   // 49 for N=50000

    // One-time side-stream + events (created during the uncaptured
    // correctness call; no device memory allocated anywhere).
    static cudaStream_t s_side = nullptr;
    static cudaEvent_t  ev_fork = nullptr, ev_join = nullptr;
    if (s_side == nullptr) {
        cudaStreamCreateWithFlags(&s_side, cudaStreamNonBlocking);
        cudaEventCreateWithFlags(&ev_fork, cudaEventDisableTiming);
        cudaEventCreateWithFlags(&ev_join, cudaEventDisableTiming);
    }

    // Fork: GEMM on side stream, concurrent with edge chain.
    cudaEventRecord(ev_fork, 0);
    cudaStreamWaitEvent(s_side, ev_fork, 0);
    dim3 gblk(32, 8);
    gemm_kernel<<<(N + 31) / 32, gblk, 0, s_side>>>(x, W, b, N);
    cudaEventRecord(ev_join, s_side);

    // Edge chain on main (captured) stream. g_cnt is zero on entry
    // (module-load init; scan3 restores it every call).
    hist_kernel<<<1184, 256>>>(row, E);
    scan1_kernel<<<nScanBlocks, SCAN_T>>>(N);
    scan2_kernel<<<1, 64>>>(nScanBlocks);
    scan3_kernel<<<nScanBlocks, SCAN_T>>>(N, E);
    scatter_kernel<<<1184, 256>>>(row, col, ew, E);

    // Join: gather needs both g_h (GEMM) and the CSR (edge chain).
    cudaStreamWaitEvent(0, ev_join, 0);
    const int threads = 256;
    gather_kernel<<<((size_t)N * 32 + threads - 1) / threads, threads>>>(out, N);
}

// round 16
// speedup vs baseline: 1.9323x; 1.0164x over previous
#include <cuda_runtime.h>
#include <math.h>

#define NMAX 50000
#define EMAX 800000
#define DF   96
// scan: 256 threads x 4 elems = 1024 elems per block
#define SCAN_T 256
#define SCAN_E 1024

// Scratch (allocation-free: __device__ globals). 16B-aligned for int4 access.
__device__ __align__(16) float g_h[NMAX * DF];     // projected features
__device__ __align__(16) int   g_cnt[NMAX];        // per-row degree (zero at entry)
__device__ __align__(16) int   g_offs[NMAX + 4];   // CSR offsets (padded)
__device__ __align__(16) int   g_cur[NMAX];        // scatter cursors
__device__ int   g_part[64];                       // per-block scan partials
__device__ __align__(16) int2  g_e[EMAX];          // packed (col, w-bits) per slot

// ---------------- dense projection: h = x @ W + b ----------------
// blockDim = (32, 8). Block tile: 32 rows x 96 cols. Thread: 4 rows x 3 cols.
__global__ void gemm_kernel(const float* __restrict__ x,
                            const float* __restrict__ W,
                            const float* __restrict__ b,
                            int N) {
    __shared__ float Ws[DF * DF];      // 36 KB
    __shared__ float xs[32][DF];       // 12 KB

    const int tx  = threadIdx.x;
    const int ty  = threadIdx.y;
    const int tid = ty * 32 + tx;

    for (int i = tid; i < DF * DF; i += 256) Ws[i] = W[i];

    const float b0 = b[tx];
    const float b1 = b[tx + 32];
    const float b2 = b[tx + 64];

    const int tile = blockIdx.x * 32;
    if (tile >= N) return;

    for (int i = tid; i < 32 * DF; i += 256) {
        int r = i / DF, c = i % DF;
        int gr = tile + r;
        xs[r][c] = (gr < N) ? x[(size_t)gr * DF + c] : 0.0f;
    }
    __syncthreads();

    const int r0 = ty * 4;
    float a[4][3];
#pragma unroll
    for (int j = 0; j < 4; j++) { a[j][0] = 0.f; a[j][1] = 0.f; a[j][2] = 0.f; }

#pragma unroll 4
    for (int k = 0; k < DF; k++) {
        float w0 = Ws[k * DF + tx];
        float w1 = Ws[k * DF + tx + 32];
        float w2 = Ws[k * DF + tx + 64];
#pragma unroll
        for (int j = 0; j < 4; j++) {
            float xv = xs[r0 + j][k];
            a[j][0] = fmaf(xv, w0, a[j][0]);
            a[j][1] = fmaf(xv, w1, a[j][1]);
            a[j][2] = fmaf(xv, w2, a[j][2]);
        }
    }

#pragma unroll
    for (int j = 0; j < 4; j++) {
        int gr = tile + r0 + j;
        if (gr < N) {
            float* hp = &g_h[(size_t)gr * DF];
            hp[tx]      = a[j][0] + b0;
            hp[tx + 32] = a[j][1] + b1;
            hp[tx + 64] = a[j][2] + b2;
        }
    }
}

// ---------------- degree histogram (int4 vectorized) ----------------
// g_cnt is zero on entry (module-load init / restored by scan3 each call).
__global__ void hist_kernel(const int* __restrict__ row, int E) {
    const int E4 = E >> 2;
    const int4* r4 = (const int4*)row;
    for (int i = blockIdx.x * blockDim.x + threadIdx.x; i < E4;
         i += gridDim.x * blockDim.x) {
        int4 v = r4[i];
        atomicAdd(&g_cnt[v.x], 1);
        atomicAdd(&g_cnt[v.y], 1);
        atomicAdd(&g_cnt[v.z], 1);
        atomicAdd(&g_cnt[v.w], 1);
    }
    for (int i = (E4 << 2) + blockIdx.x * blockDim.x + threadIdx.x; i < E;
         i += gridDim.x * blockDim.x) {
        atomicAdd(&g_cnt[row[i]], 1);
    }
}

// ---------------- scan phase 1: block-local exclusive scan (int4) --------
__global__ void scan1_kernel(int n) {
    __shared__ int warpsum[8];
    const int tid  = threadIdx.x;            // 0..255
    const int lane = tid & 31;
    const int wid  = tid >> 5;
    const int e0   = blockIdx.x * SCAN_E + tid * 4;

    int4 v;
    v.x = (e0     < n) ? g_cnt[e0]     : 0;
    v.y = (e0 + 1 < n) ? g_cnt[e0 + 1] : 0;
    v.z = (e0 + 2 < n) ? g_cnt[e0 + 2] : 0;
    v.w = (e0 + 3 < n) ? g_cnt[e0 + 3] : 0;
    const int tsum = v.x + v.y + v.z + v.w;

    // warp inclusive scan of per-thread sums
    int inc = tsum;
#pragma unroll
    for (int d = 1; d < 32; d <<= 1) {
        int t = __shfl_up_sync(0xFFFFFFFFu, inc, d);
        if (lane >= d) inc += t;
    }
    if (lane == 31) warpsum[wid] = inc;
    __syncthreads();
    if (tid < 8) {
        int ws = warpsum[tid];
#pragma unroll
        for (int d = 1; d < 8; d <<= 1) {
            int t = __shfl_up_sync(0xFFu, ws, d);
            if ((tid & 7) >= d) ws += t;
        }
        warpsum[tid] = ws;
    }
    __syncthreads();

    const int base = ((wid > 0) ? warpsum[wid - 1] : 0) + inc - tsum;

    if (e0 + 3 < n) {
        int4 o;
        o.x = base;
        o.y = base + v.x;
        o.z = o.y + v.y;
        o.w = o.z + v.z;
        *(int4*)&g_offs[e0] = o;
    } else {
        int run = base;
        if (e0     < n) { g_offs[e0]     = run; run += v.x; }
        if (e0 + 1 < n) { g_offs[e0 + 1] = run; run += v.y; }
        if (e0 + 2 < n) { g_offs[e0 + 2] = run; run += v.z; }
        if (e0 + 3 < n) { g_offs[e0 + 3] = run; }
    }
    if (tid == SCAN_T - 1) g_part[blockIdx.x] = warpsum[7];
}

// ---------------- scan phase 3': derive base in-block, finalize ----------
// Each block independently scans the <=64 partials (64 loads + shuffle scan)
// to get its own exclusive base — replaces the scan2 launch entirely.
__global__ void scan3_kernel(int n, int E, int nb) {
    __shared__ int sh_exc[64];
    const int tid = threadIdx.x;

    if (tid < 32) {
        const int i0 = 2 * tid, i1 = 2 * tid + 1;
        int a = (i0 < nb) ? g_part[i0] : 0;
        int b = (i1 < nb) ? g_part[i1] : 0;
        int s = a + b;
        int inc = s;
#pragma unroll
        for (int d = 1; d < 32; d <<= 1) {
            int t = __shfl_up_sync(0xFFFFFFFFu, inc, d);
            if (tid >= d) inc += t;
        }
        sh_exc[i0] = inc - s;        // sum of partials [0, i0)
        sh_exc[i1] = inc - b;        // sum of partials [0, i1)
    }
    __syncthreads();

    const int base = sh_exc[blockIdx.x];
    const int e0   = blockIdx.x * SCAN_E + tid * 4;
    const int4 z   = make_int4(0, 0, 0, 0);

    if (e0 + 3 < n) {
        int4 o = *(const int4*)&g_offs[e0];
        o.x += base; o.y += base; o.z += base; o.w += base;
        *(int4*)&g_offs[e0] = o;
        *(int4*)&g_cur[e0]  = o;
        *(int4*)&g_cnt[e0]  = z;         // restore invariant for next call
    } else {
#pragma unroll
        for (int j = 0; j < 4; j++) {
            int i = e0 + j;
            if (i < n) {
                int o = g_offs[i] + base;
                g_offs[i] = o;
                g_cur[i]  = o;
                g_cnt[i]  = 0;
            }
        }
    }
    if (e0 == 0) g_offs[n] = E;
}

// ---------------- bucket scatter into CSR slots (vectorized reads) -------
__global__ void scatter_kernel(const int* __restrict__ row,
                               const int* __restrict__ col,
                               const float* __restrict__ w, int E) {
    const int E4 = E >> 2;
    const int4*   r4 = (const int4*)row;
    const int4*   c4 = (const int4*)col;
    const float4* w4 = (const float4*)w;
    for (int i = blockIdx.x * blockDim.x + threadIdx.x; i < E4;
         i += gridDim.x * blockDim.x) {
        int4   r = r4[i];
        int4   c = c4[i];
        float4 wv = w4[i];
        int p;
        p = atomicAdd(&g_cur[r.x], 1); g_e[p] = make_int2(c.x, __float_as_int(wv.x));
        p = atomicAdd(&g_cur[r.y], 1); g_e[p] = make_int2(c.y, __float_as_int(wv.y));
        p = atomicAdd(&g_cur[r.z], 1); g_e[p] = make_int2(c.z, __float_as_int(wv.z));
        p = atomicAdd(&g_cur[r.w], 1); g_e[p] = make_int2(c.w, __float_as_int(wv.w));
    }
    for (int i = (E4 << 2) + blockIdx.x * blockDim.x + threadIdx.x; i < E;
         i += gridDim.x * blockDim.x) {
        int p = atomicAdd(&g_cur[row[i]], 1);
        g_e[p] = make_int2(col[i], __float_as_int(w[i]));
    }
}

// ---------------- warp-per-row gather + ELU (x4 unroll) ----------------
__global__ void gather_kernel(float* __restrict__ out, int N) {
    const int gwarp = (blockIdx.x * blockDim.x + threadIdx.x) >> 5;
    const int lane  = threadIdx.x & 31;
    if (gwarp >= N) return;

    const int s = g_offs[gwarp];
    const int e = g_offs[gwarp + 1];

    float a0 = 0.f, a1 = 0.f, a2 = 0.f;
    int i = s;
    for (; i + 3 < e; i += 4) {
        const int2 e0 = g_e[i];
        const int2 e1 = g_e[i + 1];
        const int2 e2 = g_e[i + 2];
        const int2 e3 = g_e[i + 3];
        const float* h0 = &g_h[(size_t)e0.x * DF];
        const float* h1 = &g_h[(size_t)e1.x * DF];
        const float* h2 = &g_h[(size_t)e2.x * DF];
        const float* h3 = &g_h[(size_t)e3.x * DF];
        float p00 = h0[lane], p01 = h0[lane + 32], p02 = h0[lane + 64];
        float p10 = h1[lane], p11 = h1[lane + 32], p12 = h1[lane + 64];
        float p20 = h2[lane], p21 = h2[lane + 32], p22 = h2[lane + 64];
        float p30 = h3[lane], p31 = h3[lane + 32], p32 = h3[lane + 64];
        const float w0 = __int_as_float(e0.y);
        const float w1 = __int_as_float(e1.y);
        const float w2 = __int_as_float(e2.y);
        const float w3 = __int_as_float(e3.y);
        a0 = fmaf(w0, p00, a0); a1 = fmaf(w0, p01, a1); a2 = fmaf(w0, p02, a2);
        a0 = fmaf(w1, p10, a0); a1 = fmaf(w1, p11, a1); a2 = fmaf(w1, p12, a2);
        a0 = fmaf(w2, p20, a0); a1 = fmaf(w2, p21, a1); a2 = fmaf(w2, p22, a2);
        a0 = fmaf(w3, p30, a0); a1 = fmaf(w3, p31, a1); a2 = fmaf(w3, p32, a2);
    }
    for (; i < e; i++) {
        const int2 e0 = g_e[i];
        const float wv = __int_as_float(e0.y);
        const float* hp = &g_h[(size_t)e0.x * DF];
        a0 = fmaf(wv, hp[lane],      a0);
        a1 = fmaf(wv, hp[lane + 32], a1);
        a2 = fmaf(wv, hp[lane + 64], a2);
    }

    float* pre = out;
    float* act = out + (size_t)N * DF;
    const int o = gwarp * DF + lane;
    pre[o]      = a0;
    pre[o + 32] = a1;
    pre[o + 64] = a2;
    act[o]      = (a0 > 0.f) ? a0 : expm1f(a0);
    act[o + 32] = (a1 > 0.f) ? a1 : expm1f(a1);
    act[o + 64] = (a2 > 0.f) ? a2 : expm1f(a2);
}

// ---------------- launch ----------------
extern "C" void kernel_launch(void* const* d_in, const int* in_sizes, int n_in,
                              void* d_out, int out_size) {
    const float* x  = (const float*)d_in[0];
    const float* W  = (const float*)d_in[1];
    const float* b  = (const float*)d_in[2];
    const int*   ei = (const int*)d_in[3];
    const float* ew = (const float*)d_in[4];
    float* out = (float*)d_out;

    const int N = in_sizes[0] / DF;
    const int E = in_sizes[4];
    const int* row = ei;         // edge_index[0]
    const int* col = ei + E;     // edge_index[1]

    const int nScanBlocks = (N + SCAN_E - 1) / SCAN_E;   // 49 for N=50000

    // One-time side-stream + events (created during the uncaptured
    // correctness call; no device memory allocated anywhere).
    static cudaStream_t s_side = nullptr;
    static cudaEvent_t  ev_fork = nullptr, ev_join = nullptr;
    if (s_side == nullptr) {
        cudaStreamCreateWithFlags(&s_side, cudaStreamNonBlocking);
        cudaEventCreateWithFlags(&ev_fork, cudaEventDisableTiming);
        cudaEventCreateWithFlags(&ev_join, cudaEventDisableTiming);
    }

    // Fork: GEMM on side stream, concurrent with edge chain.
    cudaEventRecord(ev_fork, 0);
    cudaStreamWaitEvent(s_side, ev_fork, 0);
    dim3 gblk(32, 8);
    gemm_kernel<<<(N + 31) / 32, gblk, 0, s_side>>>(x, W, b, N);
    cudaEventRecord(ev_join, s_side);

    // Edge chain on main (captured) stream. g_cnt is zero on entry
    // (module-load init; scan3 restores it every call).
    hist_kernel<<<1184, 256>>>(row, E);
    scan1_kernel<<<nScanBlocks, SCAN_T>>>(N);
    scan3_kernel<<<nScanBlocks, SCAN_T>>>(N, E, nScanBlocks);
    scatter_kernel<<<1184, 256>>>(row, col, ew, E);

    // Join: gather needs both g_h (GEMM) and the CSR (edge chain).
    cudaStreamWaitEvent(0, ev_join, 0);
    const int threads = 256;
    gather_kernel<<<((size_t)N * 32 + threads - 1) / threads, threads>>>(out, N);
}